// round 15
// baseline (speedup 1.0000x reference)
#include <cuda_runtime.h>
#include <math.h>
#include <stdint.h>

// Problem constants (fixed by the dataset)
#define NB 4
#define NV 4000
#define NF 6000
#define IMH 64
#define IMW 64
#define NPIX (NB * IMH * IMW)          // 16384
#define NCHUNK 48
#define FCHUNK ((NF + NCHUNK - 1) / NCHUNK)  // 125
#define TILES_PER_IMG 64               // 8x8 grid of 8x8-pixel tiles
#define NTILES (NB * TILES_PER_IMG)    // 256

#define STEPF (2.0f / 63.0f)
#define ZKEY_INIT 0xFFFFFFFFFFFFFFFFull

// -------- device scratch (no allocations allowed) --------
__device__ float              g_vscam[NB * NV * 3];
__device__ float              g_vsimg[NB * NV * 2];
__device__ float              g_vnorm[NB * NV * 3];
__device__ float4             g_rec[NB * NF * 3];   // packed raster records
__device__ float4             g_bbox[NB * NF];      // dilated bbox
__device__ float              g_accS[NPIX];         // soft-coverage log-sum
__device__ unsigned long long g_accZ[NPIX];         // packed (z_bits<<32)|face

// -------- kernels --------
__global__ void k_vertices(const float* __restrict__ verts,
                           const float* __restrict__ rot,
                           const float* __restrict__ trans) {
#if __CUDA_ARCH__ >= 900
    cudaTriggerProgrammaticLaunchCompletion();   // let successor dispatch early
#endif
    int i = blockIdx.x * blockDim.x + threadIdx.x;
    // init per-pixel accumulators (grid covers NPIX = 16384)
    if (i < NPIX) {
        g_accS[i] = 0.0f;
        g_accZ[i] = ZKEY_INIT;
    }
    if (i >= NB * NV) return;
    int b = i / NV;
    const float* v = verts + (size_t)i * 3;
    const float* R = rot + b * 9;
    const float* t = trans + b * 3;
    float x = v[0], y = v[1], z = v[2];
    float cx = x * R[0] + y * R[1] + z * R[2] + t[0];
    float cy = x * R[3] + y * R[4] + z * R[5] + t[1];
    float cz = x * R[6] + y * R[7] + z * R[8] + t[2];
    g_vscam[i * 3 + 0] = cx;
    g_vscam[i * 3 + 1] = cy;
    g_vscam[i * 3 + 2] = cz;
    g_vsimg[i * 2 + 0] = cx / cz;
    g_vsimg[i * 2 + 1] = cy / cz;
    g_vnorm[i * 3 + 0] = 0.0f;
    g_vnorm[i * 3 + 1] = 0.0f;
    g_vnorm[i * 3 + 2] = 0.0f;
}

__global__ void k_face_prep(const int* __restrict__ faces) {
#if __CUDA_ARCH__ >= 900
    cudaTriggerProgrammaticLaunchCompletion();
#endif
    int i = blockIdx.x * blockDim.x + threadIdx.x;
    if (i >= NB * NF) return;
    int b = i / NF, f = i % NF;
    int i0 = faces[f * 3 + 0], i1 = faces[f * 3 + 1], i2 = faces[f * 3 + 2];
#if __CUDA_ARCH__ >= 900
    cudaGridDependencySynchronize();             // wait for k_vertices' writes
#endif

    const float* c0 = g_vscam + ((size_t)b * NV + i0) * 3;
    const float* c1 = g_vscam + ((size_t)b * NV + i1) * 3;
    const float* c2 = g_vscam + ((size_t)b * NV + i2) * 3;
    float e1x = c1[0] - c0[0], e1y = c1[1] - c0[1], e1z = c1[2] - c0[2];
    float e2x = c2[0] - c0[0], e2y = c2[1] - c0[1], e2z = c2[2] - c0[2];
    float nx = e1y * e2z - e1z * e2y;
    float ny = e1z * e2x - e1x * e2z;
    float nz = e1x * e2y - e1y * e2x;
    atomicAdd(&g_vnorm[((size_t)b * NV + i0) * 3 + 0], nx);
    atomicAdd(&g_vnorm[((size_t)b * NV + i0) * 3 + 1], ny);
    atomicAdd(&g_vnorm[((size_t)b * NV + i0) * 3 + 2], nz);
    atomicAdd(&g_vnorm[((size_t)b * NV + i1) * 3 + 0], nx);
    atomicAdd(&g_vnorm[((size_t)b * NV + i1) * 3 + 1], ny);
    atomicAdd(&g_vnorm[((size_t)b * NV + i1) * 3 + 2], nz);
    atomicAdd(&g_vnorm[((size_t)b * NV + i2) * 3 + 0], nx);
    atomicAdd(&g_vnorm[((size_t)b * NV + i2) * 3 + 1], ny);
    atomicAdd(&g_vnorm[((size_t)b * NV + i2) * 3 + 2], nz);

    const float* p0 = g_vsimg + ((size_t)b * NV + i0) * 2;
    const float* p1 = g_vsimg + ((size_t)b * NV + i1) * 2;
    const float* p2 = g_vsimg + ((size_t)b * NV + i2) * 2;
    float v0x = p0[0], v0y = p0[1];
    float v1x = p1[0], v1y = p1[1];
    float v2x = p2[0], v2y = p2[1];
    float A = (v1x - v0x) * (v2y - v0y) - (v1y - v0y) * (v2x - v0x);
    if (fabsf(A) < 1e-8f) A = 1e-8f;
    float invA = 1.0f / A;
    float sgn  = (A > 0.0f) ? 1.0f : -1.0f;

    float4* r = g_rec + (size_t)i * 3;
    r[0] = make_float4(v0x, v0y, v1x, v1y);
    r[1] = make_float4(v2x, v2y, c0[2], c1[2]);
    r[2] = make_float4(c2[2], A, invA, sgn);

    // dilated bbox: {min_i w_i >= -0.3} == triangle scaled x1.9 about centroid
    float cx = (v0x + v1x + v2x) * 0.33333334f;
    float cy = (v0y + v1y + v2y) * 0.33333334f;
    float xmn = fminf(v0x, fminf(v1x, v2x)), xmx = fmaxf(v0x, fmaxf(v1x, v2x));
    float ymn = fminf(v0y, fminf(v1y, v2y)), ymx = fmaxf(v0y, fmaxf(v1y, v2y));
    const float SC = 1.91f, EPS = 1e-3f;
    g_bbox[i] = make_float4(cx + SC * (xmn - cx) - EPS,
                            cx + SC * (xmx - cx) + EPS,
                            cy + SC * (ymn - cy) - EPS,
                            cy + SC * (ymx - cy) + EPS);
}

__global__ __launch_bounds__(256) void k_raster() {
#if __CUDA_ARCH__ >= 900
    cudaTriggerProgrammaticLaunchCompletion();
#endif
    const int tile  = blockIdx.x;              // 0..NTILES-1
    const int chunk = blockIdx.y;              // 0..NCHUNK-1
    const int b = tile >> 6;                   // image
    const int t = tile & 63;                   // 8x8 tile grid
    const int tx = (t & 7) << 3, ty = (t >> 3) << 3;

    // warp -> (face-lane, pixel half): fl uniform per warp
    const int w    = threadIdx.x >> 5;
    const int lane = threadIdx.x & 31;
    const int fl   = w & 3;                    // face lane 0..3 (warp-uniform)
    const int half = w >> 2;                   // 0 or 1
    const int pi   = half * 32 + lane;         // pixel 0..63 within tile
    const int lx = pi & 7, ly = pi >> 3;
    const int ix = tx + lx, iy = ty + ly;
    const float px = -1.0f + ix * STEPF;
    const float py = -1.0f + iy * STEPF;
    // warp region: 8 x 4 pixels
    const float wminx = -1.0f + tx * STEPF, wmaxx = wminx + 7.0f * STEPF;
    const float wminy = -1.0f + (ty + half * 4) * STEPF, wmaxy = wminy + 3.0f * STEPF;
    // tile bounds
    const float tminx = wminx, tmaxx = wmaxx;
    const float tminy = -1.0f + ty * STEPF, tmaxy = tminy + 7.0f * STEPF;

    __shared__ int    s_cnt;
    __shared__ float4 s_r0[FCHUNK];
    __shared__ float4 s_r1[FCHUNK];
    __shared__ float4 s_r2[FCHUNK];
    __shared__ float4 s_box[FCHUNK];
    __shared__ short  s_f[FCHUNK];
    __shared__ float  red_S[256];
    __shared__ float  red_z[256];
    __shared__ int    red_i[256];
    if (threadIdx.x == 0) s_cnt = 0;
    __syncthreads();

#if __CUDA_ARCH__ >= 900
    cudaGridDependencySynchronize();           // wait for k_face_prep's writes
#endif

    const int f0 = chunk * FCHUNK;
    const int f1 = (f0 + FCHUNK < NF) ? (f0 + FCHUNK) : NF;
    const float4* bb   = g_bbox + (size_t)b * NF;
    const float4* recb = g_rec + (size_t)b * NF * 3;
    for (int f = f0 + threadIdx.x; f < f1; f += 256) {
        float4 box = bb[f];
        if (box.x <= tmaxx && box.y >= tminx && box.z <= tmaxy && box.w >= tminy) {
            int k = atomicAdd(&s_cnt, 1);
            s_box[k] = box;
            s_f[k] = (short)f;
            s_r0[k] = recb[f * 3 + 0];
            s_r1[k] = recb[f * 3 + 1];
            s_r2[k] = recb[f * 3 + 2];
        }
    }
    __syncthreads();
    const int cnt = s_cnt;
    if (cnt == 0) return;                     // cold CTA: contributes nothing

    const float K1  = 1.0f - 1e-7f;
    const float CIN = log1pf(-K1);           // inside-face contribution

    float S = 0.0f;
    float zb = INFINITY;
    int   ib = 0x7fffffff;

    for (int i = fl; i < cnt; i += 4) {
        float4 box = s_box[i];
        // warp-uniform rejection against this warp's 8x4 region
        if (box.x > wmaxx || box.y < wminx || box.z > wmaxy || box.w < wminy) continue;
        // per-pixel rejection
        if (px < box.x || px > box.y || py < box.z || py > box.w) continue;

        float4 r0 = s_r0[i];
        float4 r1 = s_r1[i];
        float4 r2 = s_r2[i];
        float v0x = r0.x, v0y = r0.y, v1x = r0.z, v1y = r0.w;
        float v2x = r1.x, v2y = r1.y, z0 = r1.z, z1 = r1.w;
        float z2 = r2.x, A = r2.y, invA = r2.z, sgn = r2.w;

        float a0 = (v2x - v1x) * (py - v1y) - (v2y - v1y) * (px - v1x);
        float a1 = (v0x - v2x) * (py - v2y) - (v0y - v2y) * (px - v2x);
        float a2 = (v1x - v0x) * (py - v0y) - (v1y - v0y) * (px - v0x);
        float c0 = a0 * sgn, c1 = a1 * sgn, c2 = a2 * sgn;  // exact sign helpers
        float cmin = fminf(c0, fminf(c1, c2));
        float invAbs = invA * sgn;                           // 1/|A| (exact flip)
        float dmin = cmin * invAbs;                          // = min_i (a_i/A) up to ulps
        if (dmin > -0.3f) {
            if (cmin >= 0.0f) {
                // inside: argmin-critical z path with exact IEEE divisions
                S += CIN;
                float w0 = a0 / A, w1 = a1 / A, w2 = a2 / A;
                float z = w0 * z0 + w1 * z1 + w2 * z2;
                int f = s_f[i];
                if (z > 0.0f && (z < zb || (z == zb && f < ib))) { zb = z; ib = f; }
            } else {
                // branch-free soft-coverage: ln(1 - p)
                float tt = fmaxf(dmin * 100.0f, -30.0f);
                float p = __expf(tt) * K1;
                S += __logf(1.0f - p);
            }
        }
    }

    // reduce across the 4 face-lanes (deterministic fl order)
    red_S[fl * 64 + pi] = S;
    red_z[fl * 64 + pi] = zb;
    red_i[fl * 64 + pi] = ib;
    __syncthreads();

    if (threadIdx.x < 64) {
        int q = threadIdx.x;              // pixel 0..63
        float Sa = red_S[q];
        float za = red_z[q];
        int   ia = red_i[q];
        #pragma unroll
        for (int l = 1; l < 4; l++) {
            Sa += red_S[l * 64 + q];
            float zo = red_z[l * 64 + q];
            int   io = red_i[l * 64 + q];
            if (zo < za || (zo == za && io < ia)) { za = zo; ia = io; }
        }
        int qx = tx + (q & 7), qy = ty + (q >> 3);
        int p = (b << 12) + (qy << 6) + qx;
        // packed lex-min: (z_bits<<32)|face — exact (z, idx) argmin semantics
        if (ia != 0x7fffffff) {
            unsigned long long key =
                ((unsigned long long)__float_as_uint(za) << 32) | (unsigned int)ia;
            atomicMin(&g_accZ[p], key);
        }
        if (Sa != 0.0f) atomicAdd(&g_accS[p], Sa);
    }
}

// 3-way vertex-parallel epilogue: thread (pixel, k), k in {0,1,2}
__global__ __launch_bounds__(192) void k_combine(const int* __restrict__ faces,
                                                 const float* __restrict__ attribs,
                                                 float* __restrict__ out) {
    const int pl = threadIdx.x & 63;          // pixel slot within CTA
    const int k  = threadIdx.x >> 6;          // vertex lane 0..2
    const int p  = blockIdx.x * 64 + pl;

    int b = p >> 12, pp = p & 4095, iy = pp >> 6, ix = pp & 63;
    float px = -1.0f + ix * STEPF;
    float py = -1.0f + iy * STEPF;

    __shared__ float s_att[3][64][6];

#if __CUDA_ARCH__ >= 900
    cudaGridDependencySynchronize();          // wait for k_raster's atomics
#endif

    unsigned long long key = g_accZ[p];
    bool covered = (key != ZKEY_INIT);

    int ib = 0;
    if (covered) {
        ib = (int)(key & 0xFFFFFFFFu);
        const float4* r = g_rec + ((size_t)b * NF + ib) * 3;
        float4 r0 = r[0], r1 = r[1];
        float v0x = r0.x, v0y = r0.y, v1x = r0.z, v1y = r0.w;
        float v2x = r1.x, v2y = r1.y;
        float A = __ldg(&r[2].y);
        float a0 = (v2x - v1x) * (py - v1y) - (v2y - v1y) * (px - v1x);
        float a1 = (v0x - v2x) * (py - v2y) - (v0y - v2y) * (px - v2x);
        float a2 = (v1x - v0x) * (py - v0y) - (v1y - v0y) * (px - v0x);
        float w0 = a0 / A, w1 = a1 / A, w2 = a2 / A;
        float wk = (k == 0) ? w0 : ((k == 1) ? w1 : w2);

        int vid = __ldg(&faces[ib * 3 + k]);
        const float* vn = g_vnorm + ((size_t)b * NV + vid) * 3;
        float x = vn[0], y = vn[1], z = vn[2];
        float d = sqrtf(x * x + y * y + z * z) + 1e-10f;
        const float* at = attribs + (((size_t)b * NF + ib) * 3 + k) * 3;
        s_att[k][pl][0] = wk * (x / d);
        s_att[k][pl][1] = wk * (y / d);
        s_att[k][pl][2] = wk * (z / d);
        s_att[k][pl][3] = wk * __ldg(&at[0]);
        s_att[k][pl][4] = wk * __ldg(&at[1]);
        s_att[k][pl][5] = wk * __ldg(&at[2]);
    }
    __syncthreads();

    if (k == 0) {
        float on0 = 0.f, on1 = 0.f, on2 = 0.f;
        float oa0 = 0.f, oa1 = 0.f, oa2 = 0.f;
        float fidx = -1.0f;
        if (covered) {
            float att[6];
            #pragma unroll
            for (int c = 0; c < 6; c++)   // fixed order k=0,1,2: bit-identical sum
                att[c] = (s_att[0][pl][c] + s_att[1][pl][c]) + s_att[2][pl][c];
            float nrm = sqrtf(att[0] * att[0] + att[1] * att[1] + att[2] * att[2]) + 1e-10f;
            on0 = att[0] / nrm; on1 = att[1] / nrm; on2 = att[2] / nrm;
            oa0 = att[3]; oa1 = att[4]; oa2 = att[5];
            fidx = (float)ib;
        }
        float improb = 1.0f - expf(g_accS[p]);

        out[p * 3 + 0] = on0;
        out[p * 3 + 1] = on1;
        out[p * 3 + 2] = on2;
        out[NPIX * 3 + p * 3 + 0] = oa0;
        out[NPIX * 3 + p * 3 + 1] = oa1;
        out[NPIX * 3 + p * 3 + 2] = oa2;
        out[NPIX * 6 + p] = improb;
        out[NPIX * 7 + p] = fidx;
    }
}

// -------- launch: PDL-chained --------
static inline void launch_pdl(void* fn, dim3 grid, dim3 block, void** args) {
    cudaLaunchConfig_t cfg = {};
    cfg.gridDim = grid;
    cfg.blockDim = block;
    cfg.dynamicSmemBytes = 0;
    cfg.stream = (cudaStream_t)0;
    cudaLaunchAttribute attr[1];
    attr[0].id = cudaLaunchAttributeProgrammaticStreamSerialization;
    attr[0].val.programmaticStreamSerializationAllowed = 1;
    cfg.attrs = attr;
    cfg.numAttrs = 1;
    cudaLaunchKernelExC(&cfg, fn, args);
}

extern "C" void kernel_launch(void* const* d_in, const int* in_sizes, int n_in,
                              void* d_out, int out_size) {
    const float* vertices = (const float*)d_in[0];
    const int*   faces    = (const int*)d_in[1];
    const float* attribs  = (const float*)d_in[2];
    const float* cam_rot  = (const float*)d_in[3];
    const float* cam_tr   = (const float*)d_in[4];
    float* out = (float*)d_out;
    (void)in_sizes; (void)n_in; (void)out_size;

    k_vertices<<<(NPIX + 255) / 256, 256>>>(vertices, cam_rot, cam_tr);

    {
        void* args[] = {(void*)&faces};
        launch_pdl((void*)k_face_prep, dim3((NB * NF + 255) / 256), dim3(256), args);
    }
    {
        void* args[] = {};
        launch_pdl((void*)k_raster, dim3(NTILES, NCHUNK), dim3(256), args);
    }
    {
        void* args[] = {(void*)&faces, (void*)&attribs, (void*)&out};
        launch_pdl((void*)k_combine, dim3(NPIX / 64), dim3(192), args);
    }
}

// round 16
// speedup vs baseline: 1.1080x; 1.1080x over previous
#include <cuda_runtime.h>
#include <math.h>
#include <stdint.h>

// Problem constants (fixed by the dataset)
#define NB 4
#define NV 4000
#define NF 6000
#define IMH 64
#define IMW 64
#define NPIX (NB * IMH * IMW)          // 16384
#define NCHUNK 48
#define FCHUNK ((NF + NCHUNK - 1) / NCHUNK)  // 125
#define TILES_PER_IMG 64               // 8x8 grid of 8x8-pixel tiles
#define NTILES (NB * TILES_PER_IMG)    // 256

#define STEPF (2.0f / 63.0f)
#define ZKEY_INIT 0xFFFFFFFFFFFFFFFFull
// soft band: faces with dmin <= -0.16 contribute <= e^{-16} ~ 1.1e-7 to S (negligible)
#define BAND_T 0.16f
#define BAND_SC 1.50f                  // bbox dilation: 1 + 3*t (+ margin)

// -------- device scratch (no allocations allowed) --------
__device__ float              g_vscam[NB * NV * 3];
__device__ float              g_vsimg[NB * NV * 2];
__device__ float              g_vnorm[NB * NV * 3];
__device__ float4             g_rec[NB * NF * 3];   // packed raster records
__device__ float4             g_bbox[NB * NF];      // dilated bbox
__device__ float              g_accS[NPIX];         // soft-coverage log-sum
__device__ unsigned long long g_accZ[NPIX];         // packed (z_bits<<32)|face

// -------- kernels --------
__global__ void k_vertices(const float* __restrict__ verts,
                           const float* __restrict__ rot,
                           const float* __restrict__ trans) {
    int i = blockIdx.x * blockDim.x + threadIdx.x;
    // init per-pixel accumulators (grid covers NPIX = 16384)
    if (i < NPIX) {
        g_accS[i] = 0.0f;
        g_accZ[i] = ZKEY_INIT;
    }
    if (i >= NB * NV) return;
    int b = i / NV;
    const float* v = verts + (size_t)i * 3;
    const float* R = rot + b * 9;
    const float* t = trans + b * 3;
    float x = v[0], y = v[1], z = v[2];
    float cx = x * R[0] + y * R[1] + z * R[2] + t[0];
    float cy = x * R[3] + y * R[4] + z * R[5] + t[1];
    float cz = x * R[6] + y * R[7] + z * R[8] + t[2];
    g_vscam[i * 3 + 0] = cx;
    g_vscam[i * 3 + 1] = cy;
    g_vscam[i * 3 + 2] = cz;
    g_vsimg[i * 2 + 0] = cx / cz;
    g_vsimg[i * 2 + 1] = cy / cz;
    g_vnorm[i * 3 + 0] = 0.0f;
    g_vnorm[i * 3 + 1] = 0.0f;
    g_vnorm[i * 3 + 2] = 0.0f;
}

__global__ void k_face_prep(const int* __restrict__ faces) {
    int i = blockIdx.x * blockDim.x + threadIdx.x;
    if (i >= NB * NF) return;
    int b = i / NF, f = i % NF;
    int i0 = faces[f * 3 + 0], i1 = faces[f * 3 + 1], i2 = faces[f * 3 + 2];

    const float* c0 = g_vscam + ((size_t)b * NV + i0) * 3;
    const float* c1 = g_vscam + ((size_t)b * NV + i1) * 3;
    const float* c2 = g_vscam + ((size_t)b * NV + i2) * 3;
    float e1x = c1[0] - c0[0], e1y = c1[1] - c0[1], e1z = c1[2] - c0[2];
    float e2x = c2[0] - c0[0], e2y = c2[1] - c0[1], e2z = c2[2] - c0[2];
    float nx = e1y * e2z - e1z * e2y;
    float ny = e1z * e2x - e1x * e2z;
    float nz = e1x * e2y - e1y * e2x;
    atomicAdd(&g_vnorm[((size_t)b * NV + i0) * 3 + 0], nx);
    atomicAdd(&g_vnorm[((size_t)b * NV + i0) * 3 + 1], ny);
    atomicAdd(&g_vnorm[((size_t)b * NV + i0) * 3 + 2], nz);
    atomicAdd(&g_vnorm[((size_t)b * NV + i1) * 3 + 0], nx);
    atomicAdd(&g_vnorm[((size_t)b * NV + i1) * 3 + 1], ny);
    atomicAdd(&g_vnorm[((size_t)b * NV + i1) * 3 + 2], nz);
    atomicAdd(&g_vnorm[((size_t)b * NV + i2) * 3 + 0], nx);
    atomicAdd(&g_vnorm[((size_t)b * NV + i2) * 3 + 1], ny);
    atomicAdd(&g_vnorm[((size_t)b * NV + i2) * 3 + 2], nz);

    const float* p0 = g_vsimg + ((size_t)b * NV + i0) * 2;
    const float* p1 = g_vsimg + ((size_t)b * NV + i1) * 2;
    const float* p2 = g_vsimg + ((size_t)b * NV + i2) * 2;
    float v0x = p0[0], v0y = p0[1];
    float v1x = p1[0], v1y = p1[1];
    float v2x = p2[0], v2y = p2[1];
    float A = (v1x - v0x) * (v2y - v0y) - (v1y - v0y) * (v2x - v0x);
    if (fabsf(A) < 1e-8f) A = 1e-8f;
    float invA = 1.0f / A;
    float sgn  = (A > 0.0f) ? 1.0f : -1.0f;

    float4* r = g_rec + (size_t)i * 3;
    r[0] = make_float4(v0x, v0y, v1x, v1y);
    r[1] = make_float4(v2x, v2y, c0[2], c1[2]);
    r[2] = make_float4(c2[2], A, invA, sgn);

    // dilated bbox: {min_i w_i >= -BAND_T} == triangle scaled (1+3t) about centroid
    float cx = (v0x + v1x + v2x) * 0.33333334f;
    float cy = (v0y + v1y + v2y) * 0.33333334f;
    float xmn = fminf(v0x, fminf(v1x, v2x)), xmx = fmaxf(v0x, fmaxf(v1x, v2x));
    float ymn = fminf(v0y, fminf(v1y, v2y)), ymx = fmaxf(v0y, fmaxf(v1y, v2y));
    const float SC = BAND_SC, EPS = 1e-3f;
    g_bbox[i] = make_float4(cx + SC * (xmn - cx) - EPS,
                            cx + SC * (xmx - cx) + EPS,
                            cy + SC * (ymn - cy) - EPS,
                            cy + SC * (ymx - cy) + EPS);
}

__global__ __launch_bounds__(256) void k_raster() {
    const int tile  = blockIdx.x;              // 0..NTILES-1
    const int chunk = blockIdx.y;              // 0..NCHUNK-1
    const int b = tile >> 6;                   // image
    const int t = tile & 63;                   // 8x8 tile grid
    const int tx = (t & 7) << 3, ty = (t >> 3) << 3;

    // warp -> (face-lane, pixel half): fl uniform per warp
    const int w    = threadIdx.x >> 5;
    const int lane = threadIdx.x & 31;
    const int fl   = w & 3;                    // face lane 0..3 (warp-uniform)
    const int half = w >> 2;                   // 0 or 1
    const int pi   = half * 32 + lane;         // pixel 0..63 within tile
    const int lx = pi & 7, ly = pi >> 3;
    const int ix = tx + lx, iy = ty + ly;
    const float px = -1.0f + ix * STEPF;
    const float py = -1.0f + iy * STEPF;
    // warp region: 8 x 4 pixels
    const float wminx = -1.0f + tx * STEPF, wmaxx = wminx + 7.0f * STEPF;
    const float wminy = -1.0f + (ty + half * 4) * STEPF, wmaxy = wminy + 3.0f * STEPF;
    // tile bounds
    const float tminx = wminx, tmaxx = wmaxx;
    const float tminy = -1.0f + ty * STEPF, tmaxy = tminy + 7.0f * STEPF;

    __shared__ int    s_cnt;
    __shared__ float4 s_r0[FCHUNK];
    __shared__ float4 s_r1[FCHUNK];
    __shared__ float4 s_r2[FCHUNK];
    __shared__ float4 s_box[FCHUNK];
    __shared__ short  s_f[FCHUNK];
    __shared__ float  red_P[256];
    __shared__ float  red_z[256];
    __shared__ int    red_i[256];
    if (threadIdx.x == 0) s_cnt = 0;
    __syncthreads();

    const int f0 = chunk * FCHUNK;
    const int f1 = (f0 + FCHUNK < NF) ? (f0 + FCHUNK) : NF;
    const float4* bb   = g_bbox + (size_t)b * NF;
    const float4* recb = g_rec + (size_t)b * NF * 3;
    for (int f = f0 + threadIdx.x; f < f1; f += 256) {
        float4 box = bb[f];
        if (box.x <= tmaxx && box.y >= tminx && box.z <= tmaxy && box.w >= tminy) {
            int k = atomicAdd(&s_cnt, 1);
            s_box[k] = box;
            s_f[k] = (short)f;
            s_r0[k] = recb[f * 3 + 0];
            s_r1[k] = recb[f * 3 + 1];
            s_r2[k] = recb[f * 3 + 2];
        }
    }
    __syncthreads();
    const int cnt = s_cnt;
    if (cnt == 0) return;                     // cold CTA: contributes nothing

    const float K1  = 1.0f - 1e-7f;
    const float OMK = 1.0f - K1;              // inside-face product factor

    float P = 1.0f;                           // product form: P = prod(1 - p_i*K1)
    float zb = INFINITY;
    int   ib = 0x7fffffff;

    for (int i = fl; i < cnt; i += 4) {
        float4 box = s_box[i];
        // warp-uniform rejection against this warp's 8x4 region
        if (box.x > wmaxx || box.y < wminx || box.z > wmaxy || box.w < wminy) continue;
        // per-pixel rejection
        if (px < box.x || px > box.y || py < box.z || py > box.w) continue;

        float4 r0 = s_r0[i];
        float4 r1 = s_r1[i];
        float4 r2 = s_r2[i];
        float v0x = r0.x, v0y = r0.y, v1x = r0.z, v1y = r0.w;
        float v2x = r1.x, v2y = r1.y, z0 = r1.z, z1 = r1.w;
        float z2 = r2.x, A = r2.y, invA = r2.z, sgn = r2.w;

        float a0 = (v2x - v1x) * (py - v1y) - (v2y - v1y) * (px - v1x);
        float a1 = (v0x - v2x) * (py - v2y) - (v0y - v2y) * (px - v2x);
        float a2 = (v1x - v0x) * (py - v0y) - (v1y - v0y) * (px - v0x);
        float c0 = a0 * sgn, c1 = a1 * sgn, c2 = a2 * sgn;  // exact sign helpers
        float cmin = fminf(c0, fminf(c1, c2));
        float invAbs = invA * sgn;                           // 1/|A| (exact flip)
        float dmin = cmin * invAbs;                          // = min_i (a_i/A) up to ulps
        if (dmin > -BAND_T) {
            if (cmin >= 0.0f) {
                // inside: argmin-critical z path with exact IEEE divisions
                P *= OMK;
                float w0 = a0 / A, w1 = a1 / A, w2 = a2 / A;
                float z = w0 * z0 + w1 * z1 + w2 * z2;
                int f = s_f[i];
                if (z > 0.0f && (z < zb || (z == zb && f < ib))) { zb = z; ib = f; }
            } else {
                // product-form soft coverage: P *= (1 - e^{dmin/sigma} * K1)
                float tt = fmaxf(dmin * 100.0f, -30.0f);
                float e = __expf(tt);
                P *= (1.0f - e * K1);
            }
        }
    }

    // reduce across the 4 face-lanes (deterministic fl order)
    red_P[fl * 64 + pi] = P;
    red_z[fl * 64 + pi] = zb;
    red_i[fl * 64 + pi] = ib;
    __syncthreads();

    if (threadIdx.x < 64) {
        int q = threadIdx.x;              // pixel 0..63
        float Pa = red_P[q];
        float za = red_z[q];
        int   ia = red_i[q];
        #pragma unroll
        for (int l = 1; l < 4; l++) {
            Pa *= red_P[l * 64 + q];
            float zo = red_z[l * 64 + q];
            int   io = red_i[l * 64 + q];
            if (zo < za || (zo == za && io < ia)) { za = zo; ia = io; }
        }
        int qx = tx + (q & 7), qy = ty + (q >> 3);
        int p = (b << 12) + (qy << 6) + qx;
        // packed lex-min: (z_bits<<32)|face — exact (z, idx) argmin semantics
        if (ia != 0x7fffffff) {
            unsigned long long key =
                ((unsigned long long)__float_as_uint(za) << 32) | (unsigned int)ia;
            atomicMin(&g_accZ[p], key);
        }
        if (Pa != 1.0f) atomicAdd(&g_accS[p], __logf(Pa));
    }
}

// 3-way vertex-parallel epilogue: thread (pixel, k), k in {0,1,2}
__global__ __launch_bounds__(192) void k_combine(const int* __restrict__ faces,
                                                 const float* __restrict__ attribs,
                                                 float* __restrict__ out) {
    const int pl = threadIdx.x & 63;          // pixel slot within CTA
    const int k  = threadIdx.x >> 6;          // vertex lane 0..2
    const int p  = blockIdx.x * 64 + pl;

    unsigned long long key = g_accZ[p];
    bool covered = (key != ZKEY_INIT);

    int b = p >> 12, pp = p & 4095, iy = pp >> 6, ix = pp & 63;
    float px = -1.0f + ix * STEPF;
    float py = -1.0f + iy * STEPF;

    __shared__ float s_att[3][64][6];

    int ib = 0;
    if (covered) {
        ib = (int)(key & 0xFFFFFFFFu);
        const float4* r = g_rec + ((size_t)b * NF + ib) * 3;
        float4 r0 = r[0], r1 = r[1];
        float v0x = r0.x, v0y = r0.y, v1x = r0.z, v1y = r0.w;
        float v2x = r1.x, v2y = r1.y;
        float A = __ldg(&r[2].y);
        float a0 = (v2x - v1x) * (py - v1y) - (v2y - v1y) * (px - v1x);
        float a1 = (v0x - v2x) * (py - v2y) - (v0y - v2y) * (px - v2x);
        float a2 = (v1x - v0x) * (py - v0y) - (v1y - v0y) * (px - v0x);
        float w0 = a0 / A, w1 = a1 / A, w2 = a2 / A;
        float wk = (k == 0) ? w0 : ((k == 1) ? w1 : w2);

        int vid = __ldg(&faces[ib * 3 + k]);
        const float* vn = g_vnorm + ((size_t)b * NV + vid) * 3;
        float x = vn[0], y = vn[1], z = vn[2];
        float d = sqrtf(x * x + y * y + z * z) + 1e-10f;
        const float* at = attribs + (((size_t)b * NF + ib) * 3 + k) * 3;
        s_att[k][pl][0] = wk * (x / d);
        s_att[k][pl][1] = wk * (y / d);
        s_att[k][pl][2] = wk * (z / d);
        s_att[k][pl][3] = wk * __ldg(&at[0]);
        s_att[k][pl][4] = wk * __ldg(&at[1]);
        s_att[k][pl][5] = wk * __ldg(&at[2]);
    }
    __syncthreads();

    if (k == 0) {
        float on0 = 0.f, on1 = 0.f, on2 = 0.f;
        float oa0 = 0.f, oa1 = 0.f, oa2 = 0.f;
        float fidx = -1.0f;
        if (covered) {
            float att[6];
            #pragma unroll
            for (int c = 0; c < 6; c++)   // fixed order k=0,1,2: bit-identical sum
                att[c] = (s_att[0][pl][c] + s_att[1][pl][c]) + s_att[2][pl][c];
            float nrm = sqrtf(att[0] * att[0] + att[1] * att[1] + att[2] * att[2]) + 1e-10f;
            on0 = att[0] / nrm; on1 = att[1] / nrm; on2 = att[2] / nrm;
            oa0 = att[3]; oa1 = att[4]; oa2 = att[5];
            fidx = (float)ib;
        }
        float improb = 1.0f - expf(g_accS[p]);

        out[p * 3 + 0] = on0;
        out[p * 3 + 1] = on1;
        out[p * 3 + 2] = on2;
        out[NPIX * 3 + p * 3 + 0] = oa0;
        out[NPIX * 3 + p * 3 + 1] = oa1;
        out[NPIX * 3 + p * 3 + 2] = oa2;
        out[NPIX * 6 + p] = improb;
        out[NPIX * 7 + p] = fidx;
    }
}

// -------- launch --------
extern "C" void kernel_launch(void* const* d_in, const int* in_sizes, int n_in,
                              void* d_out, int out_size) {
    const float* vertices = (const float*)d_in[0];
    const int*   faces    = (const int*)d_in[1];
    const float* attribs  = (const float*)d_in[2];
    const float* cam_rot  = (const float*)d_in[3];
    const float* cam_tr   = (const float*)d_in[4];
    (void)in_sizes; (void)n_in; (void)out_size;

    k_vertices<<<(NPIX + 255) / 256, 256>>>(vertices, cam_rot, cam_tr);
    k_face_prep<<<(NB * NF + 255) / 256, 256>>>(faces);
    k_raster<<<dim3(NTILES, NCHUNK), 256>>>();
    k_combine<<<NPIX / 64, 192>>>(faces, attribs, (float*)d_out);
}

// round 17
// speedup vs baseline: 1.1156x; 1.0068x over previous
#include <cuda_runtime.h>
#include <math.h>
#include <stdint.h>

// Problem constants (fixed by the dataset)
#define NB 4
#define NV 4000
#define NF 6000
#define IMH 64
#define IMW 64
#define NPIX (NB * IMH * IMW)          // 16384
#define NCHUNK 48
#define FCHUNK ((NF + NCHUNK - 1) / NCHUNK)  // 125
#define TILES_PER_IMG 64               // 8x8 grid of 8x8-pixel tiles
#define NTILES (NB * TILES_PER_IMG)    // 256

#define STEPF (2.0f / 63.0f)
// soft band: faces with dmin <= -0.16 contribute <= e^{-16} ~ 1.1e-7 to S (negligible)
#define BAND_T 0.16f
#define BAND_SC 1.50f                  // bbox dilation: 1 + 3*t (+ margin)

// -------- device scratch (no allocations allowed) --------
// Zero-initialized at module load. accZ/accS are re-zeroed by k_combine after
// each use (self-cleaning), so no init kernel is needed. vnorm is zeroed by a
// cudaMemsetAsync node each launch.
__device__ float              g_vnorm[NB * NV * 3];
__device__ float4             g_rec[NB * NF * 3];   // packed raster records
__device__ float4             g_bbox[NB * NF];      // dilated bbox
__device__ float              g_accS[NPIX];         // soft-coverage log-sum (0 = empty)
__device__ unsigned long long g_accZ[NPIX];         // COMPLEMENT of (z_bits<<32)|face; 0 = empty

// -------- fused prep: per-face vertex transform + vnorm + records --------
__global__ void k_face_prep(const float* __restrict__ verts,
                            const int* __restrict__ faces,
                            const float* __restrict__ rot,
                            const float* __restrict__ trans) {
    int i = blockIdx.x * blockDim.x + threadIdx.x;
    if (i >= NB * NF) return;
    int b = i / NF, f = i % NF;
    const float* R = rot + b * 9;
    const float* t = trans + b * 3;
    int vid[3] = {faces[f * 3 + 0], faces[f * 3 + 1], faces[f * 3 + 2]};

    // per-face vertex transform: identical expressions to a per-vertex kernel
    // -> bit-identical results (validated R8/R10/R11)
    float cxs[3], cys[3], czs[3], vx[3], vy[3];
    #pragma unroll
    for (int k = 0; k < 3; k++) {
        const float* v = verts + ((size_t)b * NV + vid[k]) * 3;
        float x = v[0], y = v[1], z = v[2];
        float cx = x * R[0] + y * R[1] + z * R[2] + t[0];
        float cy = x * R[3] + y * R[4] + z * R[5] + t[1];
        float cz = x * R[6] + y * R[7] + z * R[8] + t[2];
        cxs[k] = cx; cys[k] = cy; czs[k] = cz;
        vx[k] = cx / cz;
        vy[k] = cy / cz;
    }

    float e1x = cxs[1] - cxs[0], e1y = cys[1] - cys[0], e1z = czs[1] - czs[0];
    float e2x = cxs[2] - cxs[0], e2y = cys[2] - cys[0], e2z = czs[2] - czs[0];
    float nx = e1y * e2z - e1z * e2y;
    float ny = e1z * e2x - e1x * e2z;
    float nz = e1x * e2y - e1y * e2x;
    #pragma unroll
    for (int k = 0; k < 3; k++) {
        atomicAdd(&g_vnorm[((size_t)b * NV + vid[k]) * 3 + 0], nx);
        atomicAdd(&g_vnorm[((size_t)b * NV + vid[k]) * 3 + 1], ny);
        atomicAdd(&g_vnorm[((size_t)b * NV + vid[k]) * 3 + 2], nz);
    }

    float v0x = vx[0], v0y = vy[0];
    float v1x = vx[1], v1y = vy[1];
    float v2x = vx[2], v2y = vy[2];
    float A = (v1x - v0x) * (v2y - v0y) - (v1y - v0y) * (v2x - v0x);
    if (fabsf(A) < 1e-8f) A = 1e-8f;
    float invA = 1.0f / A;
    float sgn  = (A > 0.0f) ? 1.0f : -1.0f;

    float4* r = g_rec + (size_t)i * 3;
    r[0] = make_float4(v0x, v0y, v1x, v1y);
    r[1] = make_float4(v2x, v2y, czs[0], czs[1]);
    r[2] = make_float4(czs[2], A, invA, sgn);

    // dilated bbox: {min_i w_i >= -BAND_T} == triangle scaled (1+3t) about centroid
    float cx = (v0x + v1x + v2x) * 0.33333334f;
    float cy = (v0y + v1y + v2y) * 0.33333334f;
    float xmn = fminf(v0x, fminf(v1x, v2x)), xmx = fmaxf(v0x, fmaxf(v1x, v2x));
    float ymn = fminf(v0y, fminf(v1y, v2y)), ymx = fmaxf(v0y, fmaxf(v1y, v2y));
    const float SC = BAND_SC, EPS = 1e-3f;
    g_bbox[i] = make_float4(cx + SC * (xmn - cx) - EPS,
                            cx + SC * (xmx - cx) + EPS,
                            cy + SC * (ymn - cy) - EPS,
                            cy + SC * (ymx - cy) + EPS);
}

__global__ __launch_bounds__(256) void k_raster() {
    const int tile  = blockIdx.x;              // 0..NTILES-1
    const int chunk = blockIdx.y;              // 0..NCHUNK-1
    const int b = tile >> 6;                   // image
    const int t = tile & 63;                   // 8x8 tile grid
    const int tx = (t & 7) << 3, ty = (t >> 3) << 3;

    // warp -> (face-lane, pixel half): fl uniform per warp
    const int w    = threadIdx.x >> 5;
    const int lane = threadIdx.x & 31;
    const int fl   = w & 3;                    // face lane 0..3 (warp-uniform)
    const int half = w >> 2;                   // 0 or 1
    const int pi   = half * 32 + lane;         // pixel 0..63 within tile
    const int lx = pi & 7, ly = pi >> 3;
    const int ix = tx + lx, iy = ty + ly;
    const float px = -1.0f + ix * STEPF;
    const float py = -1.0f + iy * STEPF;
    // warp region: 8 x 4 pixels
    const float wminx = -1.0f + tx * STEPF, wmaxx = wminx + 7.0f * STEPF;
    const float wminy = -1.0f + (ty + half * 4) * STEPF, wmaxy = wminy + 3.0f * STEPF;
    // tile bounds
    const float tminx = wminx, tmaxx = wmaxx;
    const float tminy = -1.0f + ty * STEPF, tmaxy = tminy + 7.0f * STEPF;

    __shared__ int    s_cnt;
    __shared__ float4 s_r0[FCHUNK];
    __shared__ float4 s_r1[FCHUNK];
    __shared__ float4 s_r2[FCHUNK];
    __shared__ float4 s_box[FCHUNK];
    __shared__ short  s_f[FCHUNK];
    __shared__ float  red_P[256];
    __shared__ float  red_z[256];
    __shared__ int    red_i[256];
    if (threadIdx.x == 0) s_cnt = 0;
    __syncthreads();

    const int f0 = chunk * FCHUNK;
    const int f1 = (f0 + FCHUNK < NF) ? (f0 + FCHUNK) : NF;
    const float4* bb   = g_bbox + (size_t)b * NF;
    const float4* recb = g_rec + (size_t)b * NF * 3;
    for (int f = f0 + threadIdx.x; f < f1; f += 256) {
        float4 box = bb[f];
        if (box.x <= tmaxx && box.y >= tminx && box.z <= tmaxy && box.w >= tminy) {
            int k = atomicAdd(&s_cnt, 1);
            s_box[k] = box;
            s_f[k] = (short)f;
            s_r0[k] = recb[f * 3 + 0];
            s_r1[k] = recb[f * 3 + 1];
            s_r2[k] = recb[f * 3 + 2];
        }
    }
    __syncthreads();
    const int cnt = s_cnt;
    if (cnt == 0) return;                     // cold CTA: contributes nothing

    const float K1  = 1.0f - 1e-7f;
    const float OMK = 1.0f - K1;              // inside-face product factor

    float P = 1.0f;                           // product form: P = prod(1 - p_i*K1)
    float zb = INFINITY;
    int   ib = 0x7fffffff;

    for (int i = fl; i < cnt; i += 4) {
        float4 box = s_box[i];
        // warp-uniform rejection against this warp's 8x4 region
        if (box.x > wmaxx || box.y < wminx || box.z > wmaxy || box.w < wminy) continue;
        // per-pixel rejection
        if (px < box.x || px > box.y || py < box.z || py > box.w) continue;

        float4 r0 = s_r0[i];
        float4 r1 = s_r1[i];
        float4 r2 = s_r2[i];
        float v0x = r0.x, v0y = r0.y, v1x = r0.z, v1y = r0.w;
        float v2x = r1.x, v2y = r1.y, z0 = r1.z, z1 = r1.w;
        float z2 = r2.x, A = r2.y, invA = r2.z, sgn = r2.w;

        float a0 = (v2x - v1x) * (py - v1y) - (v2y - v1y) * (px - v1x);
        float a1 = (v0x - v2x) * (py - v2y) - (v0y - v2y) * (px - v2x);
        float a2 = (v1x - v0x) * (py - v0y) - (v1y - v0y) * (px - v0x);
        float c0 = a0 * sgn, c1 = a1 * sgn, c2 = a2 * sgn;  // exact sign helpers
        float cmin = fminf(c0, fminf(c1, c2));
        float invAbs = invA * sgn;                           // 1/|A| (exact flip)
        float dmin = cmin * invAbs;                          // = min_i (a_i/A) up to ulps
        if (dmin > -BAND_T) {
            if (cmin >= 0.0f) {
                // inside: argmin-critical z path with exact IEEE divisions
                P *= OMK;
                float w0 = a0 / A, w1 = a1 / A, w2 = a2 / A;
                float z = w0 * z0 + w1 * z1 + w2 * z2;
                int f = s_f[i];
                if (z > 0.0f && (z < zb || (z == zb && f < ib))) { zb = z; ib = f; }
            } else {
                // product-form soft coverage: P *= (1 - e^{dmin/sigma} * K1)
                float tt = fmaxf(dmin * 100.0f, -30.0f);
                float e = __expf(tt);
                P *= (1.0f - e * K1);
            }
        }
    }

    // reduce across the 4 face-lanes (deterministic fl order)
    red_P[fl * 64 + pi] = P;
    red_z[fl * 64 + pi] = zb;
    red_i[fl * 64 + pi] = ib;
    __syncthreads();

    if (threadIdx.x < 64) {
        int q = threadIdx.x;              // pixel 0..63
        float Pa = red_P[q];
        float za = red_z[q];
        int   ia = red_i[q];
        #pragma unroll
        for (int l = 1; l < 4; l++) {
            Pa *= red_P[l * 64 + q];
            float zo = red_z[l * 64 + q];
            int   io = red_i[l * 64 + q];
            if (zo < za || (zo == za && io < ia)) { za = zo; ia = io; }
        }
        int qx = tx + (q & 7), qy = ty + (q >> 3);
        int p = (b << 12) + (qy << 6) + qx;
        // complemented lex-min key: min(key) == max(~key); empty state = 0
        if (ia != 0x7fffffff) {
            unsigned long long key =
                ((unsigned long long)__float_as_uint(za) << 32) | (unsigned int)ia;
            atomicMax(&g_accZ[p], ~key);
        }
        if (Pa != 1.0f) atomicAdd(&g_accS[p], __logf(Pa));
    }
}

// 3-way vertex-parallel epilogue: thread (pixel, k), k in {0,1,2}
// Also self-cleans g_accZ/g_accS for the next graph replay.
__global__ __launch_bounds__(192) void k_combine(const int* __restrict__ faces,
                                                 const float* __restrict__ attribs,
                                                 float* __restrict__ out) {
    const int pl = threadIdx.x & 63;          // pixel slot within CTA
    const int k  = threadIdx.x >> 6;          // vertex lane 0..2
    const int p  = blockIdx.x * 64 + pl;

    unsigned long long keyc = g_accZ[p];
    bool covered = (keyc != 0ull);
    unsigned long long key = ~keyc;

    int b = p >> 12, pp = p & 4095, iy = pp >> 6, ix = pp & 63;
    float px = -1.0f + ix * STEPF;
    float py = -1.0f + iy * STEPF;

    __shared__ float s_att[3][64][6];

    int ib = 0;
    if (covered) {
        ib = (int)(key & 0xFFFFFFFFu);
        const float4* r = g_rec + ((size_t)b * NF + ib) * 3;
        float4 r0 = r[0], r1 = r[1];
        float v0x = r0.x, v0y = r0.y, v1x = r0.z, v1y = r0.w;
        float v2x = r1.x, v2y = r1.y;
        float A = __ldg(&r[2].y);
        float a0 = (v2x - v1x) * (py - v1y) - (v2y - v1y) * (px - v1x);
        float a1 = (v0x - v2x) * (py - v2y) - (v0y - v2y) * (px - v2x);
        float a2 = (v1x - v0x) * (py - v0y) - (v1y - v0y) * (px - v0x);
        float w0 = a0 / A, w1 = a1 / A, w2 = a2 / A;
        float wk = (k == 0) ? w0 : ((k == 1) ? w1 : w2);

        int vid = __ldg(&faces[ib * 3 + k]);
        const float* vn = g_vnorm + ((size_t)b * NV + vid) * 3;
        float x = vn[0], y = vn[1], z = vn[2];
        float d = sqrtf(x * x + y * y + z * z) + 1e-10f;
        const float* at = attribs + (((size_t)b * NF + ib) * 3 + k) * 3;
        s_att[k][pl][0] = wk * (x / d);
        s_att[k][pl][1] = wk * (y / d);
        s_att[k][pl][2] = wk * (z / d);
        s_att[k][pl][3] = wk * __ldg(&at[0]);
        s_att[k][pl][4] = wk * __ldg(&at[1]);
        s_att[k][pl][5] = wk * __ldg(&at[2]);
    }
    __syncthreads();

    if (k == 0) {
        float on0 = 0.f, on1 = 0.f, on2 = 0.f;
        float oa0 = 0.f, oa1 = 0.f, oa2 = 0.f;
        float fidx = -1.0f;
        if (covered) {
            float att[6];
            #pragma unroll
            for (int c = 0; c < 6; c++)   // fixed order k=0,1,2: bit-identical sum
                att[c] = (s_att[0][pl][c] + s_att[1][pl][c]) + s_att[2][pl][c];
            float nrm = sqrtf(att[0] * att[0] + att[1] * att[1] + att[2] * att[2]) + 1e-10f;
            on0 = att[0] / nrm; on1 = att[1] / nrm; on2 = att[2] / nrm;
            oa0 = att[3]; oa1 = att[4]; oa2 = att[5];
            fidx = (float)ib;
        }
        float improb = 1.0f - expf(g_accS[p]);

        out[p * 3 + 0] = on0;
        out[p * 3 + 1] = on1;
        out[p * 3 + 2] = on2;
        out[NPIX * 3 + p * 3 + 0] = oa0;
        out[NPIX * 3 + p * 3 + 1] = oa1;
        out[NPIX * 3 + p * 3 + 2] = oa2;
        out[NPIX * 6 + p] = improb;
        out[NPIX * 7 + p] = fidx;

        // self-clean for next replay (p is owned by this thread; all reads of
        // accZ[p]/accS[p] in this CTA happened before the __syncthreads above)
        g_accZ[p] = 0ull;
        g_accS[p] = 0.0f;
    }
}

// -------- launch --------
extern "C" void kernel_launch(void* const* d_in, const int* in_sizes, int n_in,
                              void* d_out, int out_size) {
    const float* vertices = (const float*)d_in[0];
    const int*   faces    = (const int*)d_in[1];
    const float* attribs  = (const float*)d_in[2];
    const float* cam_rot  = (const float*)d_in[3];
    const float* cam_tr   = (const float*)d_in[4];
    (void)in_sizes; (void)n_in; (void)out_size;

    static void* vnorm_ptr = nullptr;
    if (vnorm_ptr == nullptr) cudaGetSymbolAddress(&vnorm_ptr, g_vnorm);

    cudaMemsetAsync(vnorm_ptr, 0, sizeof(float) * NB * NV * 3, (cudaStream_t)0);
    k_face_prep<<<(NB * NF + 255) / 256, 256>>>(vertices, faces, cam_rot, cam_tr);
    k_raster<<<dim3(NTILES, NCHUNK), 256>>>();
    k_combine<<<NPIX / 64, 192>>>(faces, attribs, (float*)d_out);
}